// round 6
// baseline (speedup 1.0000x reference)
#include <cuda_runtime.h>
#include <math.h>

#define BB 16
#define CC 256
#define HH 224
#define WW 224
#define NPLANE (BB*CC)          // 4096 planes
#define PLANE  (HH*WW)          // 50176 floats per plane
#define PLANE4 (PLANE/4)        // 12544 float4 per plane
#define W4     (WW/4)           // 56 float4 per row

// Scratch (allocation-free rule: device globals)
__device__ float g_sums[NPLANE * 4];       // per-plane parity sums
__device__ float g_sc[NPLANE];             // per-plane output scale s[b,c]
__device__ unsigned int g_cnt[BB];         // per-batch completion counters
                                           // (zero-init at load; elected CTA
                                           //  resets its counter -> graph-replay safe)

// ---------------------------------------------------------------------------
// Kernel 1: per-plane parity-quadrant reduction + (last CTA per batch) the
// whole ori_y -> argmax -> y -> MLP -> sigmoid pipeline for that batch.
// ---------------------------------------------------------------------------
__global__ __launch_bounds__(256) void k_reduce_mlp(const float* __restrict__ x,
                                                    const float* __restrict__ w1,
                                                    const float* __restrict__ w2,
                                                    const float* __restrict__ w_enc) {
    const int plane = blockIdx.x;
    const int b = plane >> 8;
    const float4* __restrict__ xp =
        reinterpret_cast<const float4*>(x) + (size_t)plane * PLANE4;

    float4 a0 = make_float4(0.f, 0.f, 0.f, 0.f);  // even rows
    float4 a1 = make_float4(0.f, 0.f, 0.f, 0.f);  // odd rows

    #pragma unroll 4
    for (int j = threadIdx.x; j < PLANE4; j += 256) {
        float4 v = __ldcs(xp + j);
        int row = j / W4;
        if (row & 1) {
            a1.x += v.x; a1.y += v.y; a1.z += v.z; a1.w += v.w;
        } else {
            a0.x += v.x; a0.y += v.y; a0.z += v.z; a0.w += v.w;
        }
    }

    // within float4: .x/.z are even-w, .y/.w are odd-w
    float s00 = a0.x + a0.z, s01 = a0.y + a0.w;
    float s10 = a1.x + a1.z, s11 = a1.y + a1.w;

    #pragma unroll
    for (int off = 16; off; off >>= 1) {
        s00 += __shfl_xor_sync(0xffffffffu, s00, off);
        s01 += __shfl_xor_sync(0xffffffffu, s01, off);
        s10 += __shfl_xor_sync(0xffffffffu, s10, off);
        s11 += __shfl_xor_sync(0xffffffffu, s11, off);
    }

    __shared__ float ws[8][4];
    __shared__ int elected;
    int warp = threadIdx.x >> 5, lane = threadIdx.x & 31;
    if (lane == 0) {
        ws[warp][0] = s00; ws[warp][1] = s01;
        ws[warp][2] = s10; ws[warp][3] = s11;
    }
    __syncthreads();
    if (threadIdx.x < 4) {
        float t = 0.f;
        #pragma unroll
        for (int w = 0; w < 8; w++) t += ws[w][threadIdx.x];
        g_sums[plane * 4 + threadIdx.x] = t;
    }

    // ---- last-CTA-per-batch election (threadfence reduction pattern) ----
    __threadfence();
    if (threadIdx.x == 0) {
        unsigned int prev = atomicAdd(&g_cnt[b], 1u);
        elected = (prev == 255u);
        if (prev == 255u) g_cnt[b] = 0;   // reset for next graph replay
    }
    __syncthreads();
    if (!elected) return;
    __threadfence();  // acquire: make all g_sums of this batch visible

    // ---- MLP for batch b, 256 threads, one per channel ----
    const int c = threadIdx.x;
    __shared__ float ys[CC];
    __shared__ float hs[CC / 2];
    __shared__ float logits[4];
    __shared__ float wsum[8][4];

    const float scale = 0.5f / 12544.0f;  // 0.5 * 1/(112*112)

    const float4 S = *reinterpret_cast<const float4*>(g_sums + (b * CC + c) * 4);
    const float q00 = S.x, q01 = S.y, q10 = S.z, q11 = S.w;

    float oy[4];
    oy[0] = scale * ( q00 + q10 + q01 + q11);   // LL
    oy[1] = scale * (-q00 - q10 + q01 + q11);   // HL
    oy[2] = scale * (-q00 + q10 - q01 + q11);   // LH
    oy[3] = scale * ( q00 - q10 - q01 + q11);   // HH

    // logits: b_enc constant + sigmoid monotone => dropped (argmax unchanged)
    const float we = __ldg(w_enc + c);
    float p0 = oy[0] * we, p1 = oy[1] * we, p2 = oy[2] * we, p3 = oy[3] * we;
    #pragma unroll
    for (int off = 16; off; off >>= 1) {
        p0 += __shfl_xor_sync(0xffffffffu, p0, off);
        p1 += __shfl_xor_sync(0xffffffffu, p1, off);
        p2 += __shfl_xor_sync(0xffffffffu, p2, off);
        p3 += __shfl_xor_sync(0xffffffffu, p3, off);
    }
    if (lane == 0) {
        wsum[warp][0] = p0; wsum[warp][1] = p1;
        wsum[warp][2] = p2; wsum[warp][3] = p3;
    }
    __syncthreads();
    if (c < 4) {
        float t = 0.f;
        #pragma unroll
        for (int w = 0; w < 8; w++) t += wsum[w][c];
        logits[c] = t;
    }
    __syncthreads();

    // argmax over 4 bands (first max on ties, matching jnp.argmax)
    float best = logits[0];
    int   bi = 0;
    #pragma unroll
    for (int k = 1; k < 4; k++) {
        if (logits[k] > best) { best = logits[k]; bi = k; }
    }

    const float Q = oy[bi];
    float y = 0.f;
    #pragma unroll
    for (int k = 0; k < 4; k++) y += fmaxf(oy[k] - Q, 0.f);
    ys[c] = y;
    __syncthreads();

    // h = relu(y @ w1^T): w1 is (128, 256) row-major
    if (c < CC / 2) {
        float h = 0.f;
        #pragma unroll 8
        for (int i = 0; i < CC; i++) h += ys[i] * __ldg(w1 + c * CC + i);
        hs[c] = fmaxf(h, 0.f);
    }
    __syncthreads();

    // s = sigmoid(h @ w2^T): w2 is (256, 128) row-major
    float acc = 0.f;
    #pragma unroll 8
    for (int j = 0; j < CC / 2; j++) acc += hs[j] * __ldg(w2 + c * (CC / 2) + j);
    g_sc[b * CC + c] = 1.0f / (1.0f + expf(-acc));
}

// ---------------------------------------------------------------------------
// Kernel 2: out = x * s[b,c]. One CTA per plane, 256 threads, 49 float4 each,
// batched 7 loads -> 7 stores for high MLP.
// ---------------------------------------------------------------------------
__global__ __launch_bounds__(256) void k_scale(const float* __restrict__ x,
                                               float* __restrict__ out) {
    const int plane = blockIdx.x;
    const float sc = __ldg(g_sc + plane);

    const float4* __restrict__ xp =
        reinterpret_cast<const float4*>(x) + (size_t)plane * PLANE4;
    float4* __restrict__ op =
        reinterpret_cast<float4*>(out) + (size_t)plane * PLANE4;

    const int base = threadIdx.x;
    #pragma unroll
    for (int o = 0; o < 49; o += 7) {
        float4 v[7];
        #pragma unroll
        for (int u = 0; u < 7; u++)
            v[u] = __ldcs(xp + base + (o + u) * 256);
        #pragma unroll
        for (int u = 0; u < 7; u++) {
            v[u].x *= sc; v[u].y *= sc; v[u].z *= sc; v[u].w *= sc;
            __stcs(op + base + (o + u) * 256, v[u]);
        }
    }
}

// ---------------------------------------------------------------------------
extern "C" void kernel_launch(void* const* d_in, const int* in_sizes, int n_in,
                              void* d_out, int out_size) {
    const float* x     = (const float*)d_in[0];
    const float* w1    = (const float*)d_in[1];
    const float* w2    = (const float*)d_in[2];
    const float* w_enc = (const float*)d_in[3];
    // d_in[4] = b_enc: constant bias before monotone sigmoid + argmax — unused.
    float* out = (float*)d_out;

    k_reduce_mlp<<<NPLANE, 256>>>(x, w1, w2, w_enc);
    k_scale<<<NPLANE, 256>>>(x, out);
}

// round 7
// speedup vs baseline: 1.1014x; 1.1014x over previous
#include <cuda_runtime.h>
#include <math.h>

#define BB 16
#define CC 256
#define HH 224
#define WW 224
#define NPLANE (BB*CC)          // 4096 planes
#define PLANE  (HH*WW)          // 50176 floats per plane
#define PLANE4 (PLANE/4)        // 12544 float4 per plane
#define W4     (WW/4)           // 56 float4 per row

// Scratch (allocation-free rule: device globals)
__device__ float g_sums[NPLANE * 4];   // per-plane parity sums [s00,s01,s10,s11]
__device__ float g_sc[NPLANE];         // per-plane output scale s[b,c]

// ---------------------------------------------------------------------------
// Kernel 1: per-plane parity-quadrant reduction. (R1 version: 119.8us, 87% DRAM)
// ---------------------------------------------------------------------------
__global__ __launch_bounds__(256) void k_reduce(const float* __restrict__ x) {
    const int plane = blockIdx.x;
    const float4* __restrict__ xp =
        reinterpret_cast<const float4*>(x) + (size_t)plane * PLANE4;

    float4 a0 = make_float4(0.f, 0.f, 0.f, 0.f);  // even rows
    float4 a1 = make_float4(0.f, 0.f, 0.f, 0.f);  // odd rows

    #pragma unroll 4
    for (int j = threadIdx.x; j < PLANE4; j += 256) {
        float4 v = __ldcs(xp + j);
        int row = j / W4;
        if (row & 1) {
            a1.x += v.x; a1.y += v.y; a1.z += v.z; a1.w += v.w;
        } else {
            a0.x += v.x; a0.y += v.y; a0.z += v.z; a0.w += v.w;
        }
    }

    // within float4: .x/.z are even-w, .y/.w are odd-w
    float s00 = a0.x + a0.z, s01 = a0.y + a0.w;
    float s10 = a1.x + a1.z, s11 = a1.y + a1.w;

    #pragma unroll
    for (int off = 16; off; off >>= 1) {
        s00 += __shfl_xor_sync(0xffffffffu, s00, off);
        s01 += __shfl_xor_sync(0xffffffffu, s01, off);
        s10 += __shfl_xor_sync(0xffffffffu, s10, off);
        s11 += __shfl_xor_sync(0xffffffffu, s11, off);
    }

    __shared__ float ws[8][4];
    int warp = threadIdx.x >> 5, lane = threadIdx.x & 31;
    if (lane == 0) {
        ws[warp][0] = s00; ws[warp][1] = s01;
        ws[warp][2] = s10; ws[warp][3] = s11;
    }
    __syncthreads();
    if (threadIdx.x < 4) {
        float t = 0.f;
        #pragma unroll
        for (int w = 0; w < 8; w++) t += ws[w][threadIdx.x];
        g_sums[plane * 4 + threadIdx.x] = t;
    }
}

// ---------------------------------------------------------------------------
// Kernel 2: ori_y -> argmax band -> y -> 2-layer MLP -> per-channel scale.
// One CTA per batch, 256 threads (one per channel). Tiny (~5us).
// ---------------------------------------------------------------------------
__global__ __launch_bounds__(256) void k_mlp(const float* __restrict__ w1,
                                             const float* __restrict__ w2,
                                             const float* __restrict__ w_enc) {
    const int b = blockIdx.x;
    const int c = threadIdx.x;

    __shared__ float ys[CC];
    __shared__ float hs[CC / 2];
    __shared__ float logits[4];
    __shared__ float wsum[8][4];

    const float scale = 0.5f / 12544.0f;  // 0.5 * 1/(112*112)

    const float4 S = *reinterpret_cast<const float4*>(g_sums + (b * CC + c) * 4);
    const float s00 = S.x, s01 = S.y, s10 = S.z, s11 = S.w;

    float oy[4];
    oy[0] = scale * ( s00 + s10 + s01 + s11);   // LL
    oy[1] = scale * (-s00 - s10 + s01 + s11);   // HL
    oy[2] = scale * (-s00 + s10 - s01 + s11);   // LH
    oy[3] = scale * ( s00 - s10 - s01 + s11);   // HH

    // logits: b_enc constant + sigmoid monotone => dropped (argmax unchanged)
    const float we = __ldg(w_enc + c);
    float p0 = oy[0] * we, p1 = oy[1] * we, p2 = oy[2] * we, p3 = oy[3] * we;
    #pragma unroll
    for (int off = 16; off; off >>= 1) {
        p0 += __shfl_xor_sync(0xffffffffu, p0, off);
        p1 += __shfl_xor_sync(0xffffffffu, p1, off);
        p2 += __shfl_xor_sync(0xffffffffu, p2, off);
        p3 += __shfl_xor_sync(0xffffffffu, p3, off);
    }
    int warp = c >> 5, lane = c & 31;
    if (lane == 0) {
        wsum[warp][0] = p0; wsum[warp][1] = p1;
        wsum[warp][2] = p2; wsum[warp][3] = p3;
    }
    __syncthreads();
    if (c < 4) {
        float t = 0.f;
        #pragma unroll
        for (int w = 0; w < 8; w++) t += wsum[w][c];
        logits[c] = t;
    }
    __syncthreads();

    // argmax over 4 bands (first max on ties, matching jnp.argmax)
    float best = logits[0];
    int   bi = 0;
    #pragma unroll
    for (int k = 1; k < 4; k++) {
        if (logits[k] > best) { best = logits[k]; bi = k; }
    }

    const float Q = oy[bi];
    float y = 0.f;
    #pragma unroll
    for (int k = 0; k < 4; k++) y += fmaxf(oy[k] - Q, 0.f);
    ys[c] = y;
    __syncthreads();

    // h = relu(y @ w1^T): w1 is (128, 256) row-major
    if (c < CC / 2) {
        float h = 0.f;
        #pragma unroll 8
        for (int i = 0; i < CC; i++) h += ys[i] * __ldg(w1 + c * CC + i);
        hs[c] = fmaxf(h, 0.f);
    }
    __syncthreads();

    // s = sigmoid(h @ w2^T): w2 is (256, 128) row-major
    float acc = 0.f;
    #pragma unroll 8
    for (int j = 0; j < CC / 2; j++) acc += hs[j] * __ldg(w2 + c * (CC / 2) + j);
    g_sc[b * CC + c] = 1.0f / (1.0f + expf(-acc));
}

// ---------------------------------------------------------------------------
// Kernel 3: out = x * s[b,c]. One CTA per plane, 256 threads, 49 float4 each,
// batched 7 loads -> 7 stores. (R6-proven: 239.5us, 83.9% DRAM)
// ---------------------------------------------------------------------------
__global__ __launch_bounds__(256) void k_scale(const float* __restrict__ x,
                                               float* __restrict__ out) {
    const int plane = blockIdx.x;
    const float sc = __ldg(g_sc + plane);

    const float4* __restrict__ xp =
        reinterpret_cast<const float4*>(x) + (size_t)plane * PLANE4;
    float4* __restrict__ op =
        reinterpret_cast<float4*>(out) + (size_t)plane * PLANE4;

    const int base = threadIdx.x;
    #pragma unroll
    for (int o = 0; o < 49; o += 7) {
        float4 v[7];
        #pragma unroll
        for (int u = 0; u < 7; u++)
            v[u] = __ldcs(xp + base + (o + u) * 256);
        #pragma unroll
        for (int u = 0; u < 7; u++) {
            v[u].x *= sc; v[u].y *= sc; v[u].z *= sc; v[u].w *= sc;
            __stcs(op + base + (o + u) * 256, v[u]);
        }
    }
}

// ---------------------------------------------------------------------------
extern "C" void kernel_launch(void* const* d_in, const int* in_sizes, int n_in,
                              void* d_out, int out_size) {
    const float* x     = (const float*)d_in[0];
    const float* w1    = (const float*)d_in[1];
    const float* w2    = (const float*)d_in[2];
    const float* w_enc = (const float*)d_in[3];
    // d_in[4] = b_enc: constant bias before monotone sigmoid + argmax — unused.
    float* out = (float*)d_out;

    k_reduce<<<NPLANE, 256>>>(x);
    k_mlp<<<BB, 256>>>(w1, w2, w_enc);
    k_scale<<<NPLANE, 256>>>(x, out);
}

// round 12
// speedup vs baseline: 1.1492x; 1.0434x over previous
#include <cuda_runtime.h>
#include <math.h>

#define BB 16
#define CC 256
#define HH 224
#define WW 224
#define NPLANE (BB*CC)          // 4096 planes
#define PLANE  (HH*WW)          // 50176 floats per plane
#define PLANE4 (PLANE/4)        // 12544 float4 per plane
#define W4     (WW/4)           // 56 float4 per row
#define KEEP_START 3584         // planes [3584,4096): ~100MB kept L2-resident

// Scratch (allocation-free rule: device globals)
__device__ float g_sums[NPLANE * 4];   // per-plane parity sums [s00,s01,s10,s11]
__device__ float g_sc[NPLANE];         // per-plane output scale s[b,c]

// ---------------------------------------------------------------------------
// Kernel 1: per-plane parity-quadrant reduction.
// Planes < KEEP_START stream (__ldcs, evict-first); planes >= KEEP_START use
// default policy so they remain in L2 for k_scale's first (reversed) wave.
// ---------------------------------------------------------------------------
__global__ __launch_bounds__(256) void k_reduce(const float* __restrict__ x) {
    const int plane = blockIdx.x;
    const float4* __restrict__ xp =
        reinterpret_cast<const float4*>(x) + (size_t)plane * PLANE4;

    float4 a0 = make_float4(0.f, 0.f, 0.f, 0.f);  // even rows
    float4 a1 = make_float4(0.f, 0.f, 0.f, 0.f);  // odd rows

    if (plane >= KEEP_START) {
        #pragma unroll 4
        for (int j = threadIdx.x; j < PLANE4; j += 256) {
            float4 v = __ldg(xp + j);          // default policy -> L2 resident
            int row = j / W4;
            if (row & 1) {
                a1.x += v.x; a1.y += v.y; a1.z += v.z; a1.w += v.w;
            } else {
                a0.x += v.x; a0.y += v.y; a0.z += v.z; a0.w += v.w;
            }
        }
    } else {
        #pragma unroll 4
        for (int j = threadIdx.x; j < PLANE4; j += 256) {
            float4 v = __ldcs(xp + j);         // streaming, evict-first
            int row = j / W4;
            if (row & 1) {
                a1.x += v.x; a1.y += v.y; a1.z += v.z; a1.w += v.w;
            } else {
                a0.x += v.x; a0.y += v.y; a0.z += v.z; a0.w += v.w;
            }
        }
    }

    // within float4: .x/.z are even-w, .y/.w are odd-w
    float s00 = a0.x + a0.z, s01 = a0.y + a0.w;
    float s10 = a1.x + a1.z, s11 = a1.y + a1.w;

    #pragma unroll
    for (int off = 16; off; off >>= 1) {
        s00 += __shfl_xor_sync(0xffffffffu, s00, off);
        s01 += __shfl_xor_sync(0xffffffffu, s01, off);
        s10 += __shfl_xor_sync(0xffffffffu, s10, off);
        s11 += __shfl_xor_sync(0xffffffffu, s11, off);
    }

    __shared__ float ws[8][4];
    int warp = threadIdx.x >> 5, lane = threadIdx.x & 31;
    if (lane == 0) {
        ws[warp][0] = s00; ws[warp][1] = s01;
        ws[warp][2] = s10; ws[warp][3] = s11;
    }
    __syncthreads();
    if (threadIdx.x < 4) {
        float t = 0.f;
        #pragma unroll
        for (int w = 0; w < 8; w++) t += ws[w][threadIdx.x];
        g_sums[plane * 4 + threadIdx.x] = t;
    }
}

// ---------------------------------------------------------------------------
// Kernel 2: ori_y -> argmax band -> y -> 2-layer MLP -> per-channel scale.
// One CTA per batch, 256 threads. float4 weight loads.
// ---------------------------------------------------------------------------
__global__ __launch_bounds__(256) void k_mlp(const float* __restrict__ w1,
                                             const float* __restrict__ w2,
                                             const float* __restrict__ w_enc) {
    const int b = blockIdx.x;
    const int c = threadIdx.x;

    __shared__ float ys[CC];
    __shared__ float hs[CC / 2];
    __shared__ float logits[4];
    __shared__ float wsum[8][4];

    const float scale = 0.5f / 12544.0f;  // 0.5 * 1/(112*112)

    const float4 S = *reinterpret_cast<const float4*>(g_sums + (b * CC + c) * 4);
    const float s00 = S.x, s01 = S.y, s10 = S.z, s11 = S.w;

    float oy[4];
    oy[0] = scale * ( s00 + s10 + s01 + s11);   // LL
    oy[1] = scale * (-s00 - s10 + s01 + s11);   // HL
    oy[2] = scale * (-s00 + s10 - s01 + s11);   // LH
    oy[3] = scale * ( s00 - s10 - s01 + s11);   // HH

    // logits: b_enc constant + sigmoid monotone => dropped (argmax unchanged)
    const float we = __ldg(w_enc + c);
    float p0 = oy[0] * we, p1 = oy[1] * we, p2 = oy[2] * we, p3 = oy[3] * we;
    #pragma unroll
    for (int off = 16; off; off >>= 1) {
        p0 += __shfl_xor_sync(0xffffffffu, p0, off);
        p1 += __shfl_xor_sync(0xffffffffu, p1, off);
        p2 += __shfl_xor_sync(0xffffffffu, p2, off);
        p3 += __shfl_xor_sync(0xffffffffu, p3, off);
    }
    int warp = c >> 5, lane = c & 31;
    if (lane == 0) {
        wsum[warp][0] = p0; wsum[warp][1] = p1;
        wsum[warp][2] = p2; wsum[warp][3] = p3;
    }
    __syncthreads();
    if (c < 4) {
        float t = 0.f;
        #pragma unroll
        for (int w = 0; w < 8; w++) t += wsum[w][c];
        logits[c] = t;
    }
    __syncthreads();

    // argmax over 4 bands (first max on ties, matching jnp.argmax)
    float best = logits[0];
    int   bi = 0;
    #pragma unroll
    for (int k = 1; k < 4; k++) {
        if (logits[k] > best) { best = logits[k]; bi = k; }
    }

    const float Q = oy[bi];
    float y = 0.f;
    #pragma unroll
    for (int k = 0; k < 4; k++) y += fmaxf(oy[k] - Q, 0.f);
    ys[c] = y;
    __syncthreads();

    // h = relu(y @ w1^T): w1 is (128, 256) row-major, float4 loads
    if (c < CC / 2) {
        const float4* w1r = reinterpret_cast<const float4*>(w1 + c * CC);
        const float4* ysv = reinterpret_cast<const float4*>(ys);
        float h = 0.f;
        #pragma unroll 8
        for (int i = 0; i < CC / 4; i++) {
            float4 wv = __ldg(w1r + i);
            float4 yv = ysv[i];
            h += wv.x * yv.x + wv.y * yv.y + wv.z * yv.z + wv.w * yv.w;
        }
        hs[c] = fmaxf(h, 0.f);
    }
    __syncthreads();

    // s = sigmoid(h @ w2^T): w2 is (256, 128) row-major, float4 loads
    {
        const float4* w2r = reinterpret_cast<const float4*>(w2 + c * (CC / 2));
        const float4* hsv = reinterpret_cast<const float4*>(hs);
        float acc = 0.f;
        #pragma unroll 8
        for (int j = 0; j < CC / 8; j++) {
            float4 wv = __ldg(w2r + j);
            float4 hv = hsv[j];
            acc += wv.x * hv.x + wv.y * hv.y + wv.z * hv.z + wv.w * hv.w;
        }
        g_sc[b * CC + c] = 1.0f / (1.0f + expf(-acc));
    }
}

// ---------------------------------------------------------------------------
// Kernel 3: out = x * s[b,c]. One CTA per plane, reversed plane order so the
// first wave consumes the L2-retained tail planes. 256 threads, 49 float4
// each, batched 7 loads -> 7 stores.
// ---------------------------------------------------------------------------
__global__ __launch_bounds__(256) void k_scale(const float* __restrict__ x,
                                               float* __restrict__ out) {
    const int plane = (NPLANE - 1) - blockIdx.x;   // reverse order
    const float sc = __ldg(g_sc + plane);

    const float4* __restrict__ xp =
        reinterpret_cast<const float4*>(x) + (size_t)plane * PLANE4;
    float4* __restrict__ op =
        reinterpret_cast<float4*>(out) + (size_t)plane * PLANE4;

    const int base = threadIdx.x;
    if (plane >= KEEP_START) {
        // L2-resident window: normal loads (hit in L2)
        #pragma unroll
        for (int o = 0; o < 49; o += 7) {
            float4 v[7];
            #pragma unroll
            for (int u = 0; u < 7; u++)
                v[u] = __ldg(xp + base + (o + u) * 256);
            #pragma unroll
            for (int u = 0; u < 7; u++) {
                v[u].x *= sc; v[u].y *= sc; v[u].z *= sc; v[u].w *= sc;
                __stcs(op + base + (o + u) * 256, v[u]);
            }
        }
    } else {
        #pragma unroll
        for (int o = 0; o < 49; o += 7) {
            float4 v[7];
            #pragma unroll
            for (int u = 0; u < 7; u++)
                v[u] = __ldcs(xp + base + (o + u) * 256);
            #pragma unroll
            for (int u = 0; u < 7; u++) {
                v[u].x *= sc; v[u].y *= sc; v[u].z *= sc; v[u].w *= sc;
                __stcs(op + base + (o + u) * 256, v[u]);
            }
        }
    }
}

// ---------------------------------------------------------------------------
extern "C" void kernel_launch(void* const* d_in, const int* in_sizes, int n_in,
                              void* d_out, int out_size) {
    const float* x     = (const float*)d_in[0];
    const float* w1    = (const float*)d_in[1];
    const float* w2    = (const float*)d_in[2];
    const float* w_enc = (const float*)d_in[3];
    // d_in[4] = b_enc: constant bias before monotone sigmoid + argmax — unused.
    float* out = (float*)d_out;

    k_reduce<<<NPLANE, 256>>>(x);
    k_mlp<<<BB, 256>>>(w1, w2, w_enc);
    k_scale<<<NPLANE, 256>>>(x, out);
}

// round 13
// speedup vs baseline: 1.1776x; 1.0247x over previous
#include <cuda_runtime.h>
#include <math.h>

#define BB 16
#define CC 256
#define HH 224
#define WW 224
#define NPLANE (BB*CC)          // 4096 planes
#define PLANE  (HH*WW)          // 50176 floats per plane
#define PLANE4 (PLANE/4)        // 12544 float4 per plane
#define W4     (WW/4)           // 56 float4 per row
#define KEEP_START 3520         // planes [3520,4096): 576 planes ~115.6MB L2-resident

// Scratch (allocation-free rule: device globals)
__device__ float g_sums[NPLANE * 4];   // per-plane parity sums [s00,s01,s10,s11]
__device__ float g_sc[NPLANE];         // per-plane output scale s[b,c]

// ---------------------------------------------------------------------------
// Kernel 1: per-plane parity-quadrant reduction.
// Planes < KEEP_START stream (__ldcs, evict-first); planes >= KEEP_START use
// default policy so they remain in L2 for k_scale's first (reversed) wave.
// ---------------------------------------------------------------------------
__global__ __launch_bounds__(256) void k_reduce(const float* __restrict__ x) {
    const int plane = blockIdx.x;
    const float4* __restrict__ xp =
        reinterpret_cast<const float4*>(x) + (size_t)plane * PLANE4;

    float4 a0 = make_float4(0.f, 0.f, 0.f, 0.f);  // even rows
    float4 a1 = make_float4(0.f, 0.f, 0.f, 0.f);  // odd rows

    if (plane >= KEEP_START) {
        #pragma unroll 4
        for (int j = threadIdx.x; j < PLANE4; j += 256) {
            float4 v = __ldg(xp + j);          // default policy -> L2 resident
            int row = j / W4;
            if (row & 1) {
                a1.x += v.x; a1.y += v.y; a1.z += v.z; a1.w += v.w;
            } else {
                a0.x += v.x; a0.y += v.y; a0.z += v.z; a0.w += v.w;
            }
        }
    } else {
        #pragma unroll 4
        for (int j = threadIdx.x; j < PLANE4; j += 256) {
            float4 v = __ldcs(xp + j);         // streaming, evict-first
            int row = j / W4;
            if (row & 1) {
                a1.x += v.x; a1.y += v.y; a1.z += v.z; a1.w += v.w;
            } else {
                a0.x += v.x; a0.y += v.y; a0.z += v.z; a0.w += v.w;
            }
        }
    }

    // within float4: .x/.z are even-w, .y/.w are odd-w
    float s00 = a0.x + a0.z, s01 = a0.y + a0.w;
    float s10 = a1.x + a1.z, s11 = a1.y + a1.w;

    #pragma unroll
    for (int off = 16; off; off >>= 1) {
        s00 += __shfl_xor_sync(0xffffffffu, s00, off);
        s01 += __shfl_xor_sync(0xffffffffu, s01, off);
        s10 += __shfl_xor_sync(0xffffffffu, s10, off);
        s11 += __shfl_xor_sync(0xffffffffu, s11, off);
    }

    __shared__ float ws[8][4];
    int warp = threadIdx.x >> 5, lane = threadIdx.x & 31;
    if (lane == 0) {
        ws[warp][0] = s00; ws[warp][1] = s01;
        ws[warp][2] = s10; ws[warp][3] = s11;
    }
    __syncthreads();
    if (threadIdx.x < 4) {
        float t = 0.f;
        #pragma unroll
        for (int w = 0; w < 8; w++) t += ws[w][threadIdx.x];
        g_sums[plane * 4 + threadIdx.x] = t;
    }
    // Let the dependent k_mlp launch as soon as this grid's stores are visible.
    cudaTriggerProgrammaticLaunchCompletion();
}

// ---------------------------------------------------------------------------
// Kernel 2: ori_y -> argmax band -> y -> 2-layer MLP -> per-channel scale.
// One CTA per batch, 256 threads. PDL: waits on k_reduce's writes.
// ---------------------------------------------------------------------------
__global__ __launch_bounds__(256) void k_mlp(const float* __restrict__ w1,
                                             const float* __restrict__ w2,
                                             const float* __restrict__ w_enc) {
    const int b = blockIdx.x;
    const int c = threadIdx.x;

    __shared__ float ys[CC];
    __shared__ float hs[CC / 2];
    __shared__ float logits[4];
    __shared__ float wsum[8][4];

    // Prefetch weights (no dependency on k_reduce) before waiting.
    const float we = __ldg(w_enc + c);

    cudaGridDependencySynchronize();   // g_sums fully written

    const float scale = 0.5f / 12544.0f;  // 0.5 * 1/(112*112)

    const float4 S = *reinterpret_cast<const float4*>(g_sums + (b * CC + c) * 4);
    const float s00 = S.x, s01 = S.y, s10 = S.z, s11 = S.w;

    float oy[4];
    oy[0] = scale * ( s00 + s10 + s01 + s11);   // LL
    oy[1] = scale * (-s00 - s10 + s01 + s11);   // HL
    oy[2] = scale * (-s00 + s10 - s01 + s11);   // LH
    oy[3] = scale * ( s00 - s10 - s01 + s11);   // HH

    // logits: b_enc constant + sigmoid monotone => dropped (argmax unchanged)
    float p0 = oy[0] * we, p1 = oy[1] * we, p2 = oy[2] * we, p3 = oy[3] * we;
    #pragma unroll
    for (int off = 16; off; off >>= 1) {
        p0 += __shfl_xor_sync(0xffffffffu, p0, off);
        p1 += __shfl_xor_sync(0xffffffffu, p1, off);
        p2 += __shfl_xor_sync(0xffffffffu, p2, off);
        p3 += __shfl_xor_sync(0xffffffffu, p3, off);
    }
    int warp = c >> 5, lane = c & 31;
    if (lane == 0) {
        wsum[warp][0] = p0; wsum[warp][1] = p1;
        wsum[warp][2] = p2; wsum[warp][3] = p3;
    }
    __syncthreads();
    if (c < 4) {
        float t = 0.f;
        #pragma unroll
        for (int w = 0; w < 8; w++) t += wsum[w][c];
        logits[c] = t;
    }
    __syncthreads();

    // argmax over 4 bands (first max on ties, matching jnp.argmax)
    float best = logits[0];
    int   bi = 0;
    #pragma unroll
    for (int k = 1; k < 4; k++) {
        if (logits[k] > best) { best = logits[k]; bi = k; }
    }

    const float Q = oy[bi];
    float y = 0.f;
    #pragma unroll
    for (int k = 0; k < 4; k++) y += fmaxf(oy[k] - Q, 0.f);
    ys[c] = y;
    __syncthreads();

    // h = relu(y @ w1^T): w1 is (128, 256) row-major, float4 loads
    if (c < CC / 2) {
        const float4* w1r = reinterpret_cast<const float4*>(w1 + c * CC);
        const float4* ysv = reinterpret_cast<const float4*>(ys);
        float h = 0.f;
        #pragma unroll 8
        for (int i = 0; i < CC / 4; i++) {
            float4 wv = __ldg(w1r + i);
            float4 yv = ysv[i];
            h += wv.x * yv.x + wv.y * yv.y + wv.z * yv.z + wv.w * yv.w;
        }
        hs[c] = fmaxf(h, 0.f);
    }
    __syncthreads();

    // s = sigmoid(h @ w2^T): w2 is (256, 128) row-major, float4 loads
    {
        const float4* w2r = reinterpret_cast<const float4*>(w2 + c * (CC / 2));
        const float4* hsv = reinterpret_cast<const float4*>(hs);
        float acc = 0.f;
        #pragma unroll 8
        for (int j = 0; j < CC / 8; j++) {
            float4 wv = __ldg(w2r + j);
            float4 hv = hsv[j];
            acc += wv.x * hv.x + wv.y * hv.y + wv.z * hv.z + wv.w * hv.w;
        }
        g_sc[b * CC + c] = 1.0f / (1.0f + expf(-acc));
    }
    cudaTriggerProgrammaticLaunchCompletion();
}

// ---------------------------------------------------------------------------
// Kernel 3: out = x * s[b,c]. One CTA per plane, reversed plane order so the
// first wave consumes the L2-retained tail planes. PDL: prefetches the first
// 7 x-loads (independent of k_mlp) before waiting on g_sc.
// ---------------------------------------------------------------------------
template <bool RESIDENT>
__device__ __forceinline__ void scale_body(const float4* __restrict__ xp,
                                           float4* __restrict__ op,
                                           int plane) {
    const int base = threadIdx.x;

    // Prefetch batch 0 before the cross-grid dependency wait (x is an input,
    // independent of k_mlp's output).
    float4 v[7];
    #pragma unroll
    for (int u = 0; u < 7; u++)
        v[u] = RESIDENT ? __ldg(xp + base + u * 256)
                        : __ldcs(xp + base + u * 256);

    cudaGridDependencySynchronize();   // g_sc ready
    const float sc = __ldg(g_sc + plane);

    #pragma unroll
    for (int o = 0; o < 49; o += 7) {
        float4 w[7];
        if (o + 7 < 49) {
            #pragma unroll
            for (int u = 0; u < 7; u++)
                w[u] = RESIDENT ? __ldg(xp + base + (o + 7 + u) * 256)
                                : __ldcs(xp + base + (o + 7 + u) * 256);
        }
        #pragma unroll
        for (int u = 0; u < 7; u++) {
            v[u].x *= sc; v[u].y *= sc; v[u].z *= sc; v[u].w *= sc;
            __stcs(op + base + (o + u) * 256, v[u]);
        }
        #pragma unroll
        for (int u = 0; u < 7; u++) v[u] = w[u];
    }
}

__global__ __launch_bounds__(256) void k_scale(const float* __restrict__ x,
                                               float* __restrict__ out) {
    const int plane = (NPLANE - 1) - blockIdx.x;   // reverse order
    const float4* __restrict__ xp =
        reinterpret_cast<const float4*>(x) + (size_t)plane * PLANE4;
    float4* __restrict__ op =
        reinterpret_cast<float4*>(out) + (size_t)plane * PLANE4;

    if (plane >= KEEP_START) scale_body<true>(xp, op, plane);
    else                     scale_body<false>(xp, op, plane);
}

// ---------------------------------------------------------------------------
extern "C" void kernel_launch(void* const* d_in, const int* in_sizes, int n_in,
                              void* d_out, int out_size) {
    const float* x     = (const float*)d_in[0];
    const float* w1    = (const float*)d_in[1];
    const float* w2    = (const float*)d_in[2];
    const float* w_enc = (const float*)d_in[3];
    // d_in[4] = b_enc: constant bias before monotone sigmoid + argmax — unused.
    float* out = (float*)d_out;

    k_reduce<<<NPLANE, 256>>>(x);

    cudaLaunchAttribute attr[1];
    attr[0].id = cudaLaunchAttributeProgrammaticStreamSerialization;
    attr[0].val.programmaticStreamSerializationAllowed = 1;

    {
        cudaLaunchConfig_t cfg = {};
        cfg.gridDim = dim3(BB);
        cfg.blockDim = dim3(256);
        cfg.attrs = attr;
        cfg.numAttrs = 1;
        cudaLaunchKernelEx(&cfg, k_mlp, w1, w2, w_enc);
    }
    {
        cudaLaunchConfig_t cfg = {};
        cfg.gridDim = dim3(NPLANE);
        cfg.blockDim = dim3(256);
        cfg.attrs = attr;
        cfg.numAttrs = 1;
        cudaLaunchKernelEx(&cfg, k_scale, x, out);
    }
}